// round 13
// baseline (speedup 1.0000x reference)
#include <cuda_runtime.h>
#include <math.h>

#define T_SEQ 512
#define NB    64
#define NI    256
#define NH    512

// Per (group, jt) progress flags, 256 B apart. MONOTONIC across graph
// replays: each launch adds exactly T_SEQ to every flag (single writer),
// so all flags are equal at every launch boundary; a CTA reads one of its
// own flags (unwritten yet this launch) as the base.
__device__ unsigned g_prog[256 * 64];

typedef unsigned long long ull;

// Packed 2x fp32 FMA (sm_10x f32x2 pipe).
#define FFMA2(d, a, b, c) \
    asm("fma.rn.f32x2 %0, %1, %2, %3;" : "=l"(d) : "l"(a), "l"(b), "l"(c))

__device__ __forceinline__ float2 unpack2(ull v) {
    unsigned lo, hi;
    asm("mov.b64 {%0, %1}, %2;" : "=r"(lo), "=r"(hi) : "l"(v));
    return make_float2(__uint_as_float(lo), __uint_as_float(hi));
}

__device__ __forceinline__ unsigned smem_u32(const void* p) {
    return (unsigned)__cvta_generic_to_shared(p);
}
__device__ __forceinline__ void mbar_init(unsigned a, unsigned cnt) {
    asm volatile("mbarrier.init.shared.b64 [%0], %1;" :: "r"(a), "r"(cnt)
                 : "memory");
}
__device__ __forceinline__ void mbar_arrive(unsigned a) {
    asm volatile("mbarrier.arrive.release.cta.shared.b64 _, [%0];"
                 :: "r"(a) : "memory");
}
__device__ __forceinline__ void mbar_wait(unsigned a, unsigned parity) {
    unsigned done;
    do {
        asm volatile(
            "{\n\t.reg .pred p;\n\t"
            "mbarrier.try_wait.parity.acquire.cta.shared.b64 p, [%1], %2, 0x989680;\n\t"
            "selp.b32 %0, 1, 0, p;\n\t}"
            : "=r"(done) : "r"(a), "r"(parity) : "memory");
    } while (!done);
}
// Poll a progress flag until it reaches `need` (acquire orders later loads).
__device__ __forceinline__ void flag_wait(const unsigned* f, unsigned need) {
    unsigned v;
    do {
        asm volatile("ld.acquire.gpu.u32 %0, [%1];"
                     : "=r"(v) : "l"(f) : "memory");
    } while ((int)(v - need) < 0);
}

// ---- dynamic smem layout (float indices) ----------------------------------
#define HS_OFF    0       // h tile [8 b][512]                  (16 KB)
#define PART_OFF  4096    // consumer partials [8 ks][4 b][32]  ( 4 KB)
#define RING_OFF  6144    // pre ring [2 slot][8 b][32 j]       ( 2 KB)
#define XB_OFF    6656    // x tile [8 b][256]                  ( 8 KB)
#define PP_OFF    8704    // producer partials [4 pw][8 b][32]  ( 4 KB)
#define MBAR_OFF  9728    // full0, full1, empty0, empty1 (4x u64) + base
#define SM_FLOATS 9744

#define RT 384   // warps 0..7 consumers (256 thr), warps 8..11 producers

__global__ __launch_bounds__(RT, 1) void rnn_fused(
    const float* __restrict__ x,     // [T][B][I]
    const float* __restrict__ h0,    // [B][H]
    const float* __restrict__ Wih,   // [H][I]
    const float* __restrict__ Whh,   // [H][H]
    const float* __restrict__ bih,   // [H]
    const float* __restrict__ bhh,   // [H]
    float* __restrict__ hseq,        // [T][B][H]
    float* __restrict__ hlast)       // [B][H] or nullptr
{
    extern __shared__ float sm[];

    const int tid  = threadIdx.x;
    const int lane = tid & 31;
    const int warp = tid >> 5;
    const int jt   = blockIdx.x & 15;
    const int gp   = blockIdx.x >> 4;     // group pair 0..7
    const int j0   = jt * 32;
    const int b0   = gp * 8;              // batches b0..b0+3 = group 2gp,
                                          //         b0+4..b0+7 = group 2gp+1
    const int gA   = 2 * gp;
    const int gB   = 2 * gp + 1;

    unsigned* const flagA_own = &g_prog[(gA * 16 + jt) * 64];
    unsigned* const flagB_own = &g_prog[(gB * 16 + jt) * 64];

    const unsigned a_full0  = smem_u32(sm + MBAR_OFF);       // +0 / +8
    const unsigned a_empty0 = smem_u32(sm + MBAR_OFF + 4);   // +0 / +8
    unsigned* const pbase   = (unsigned*)(sm + MBAR_OFF + 8);

    if (tid == 0) {
        mbar_init(a_full0,      4);   // 4 producer warps arrive
        mbar_init(a_full0  + 8, 4);
        mbar_init(a_empty0,     8);   // 8 consumer warps arrive
        mbar_init(a_empty0 + 8, 8);
        *pbase = *(volatile unsigned*)flagA_own;   // launch base
    }
    __syncthreads();
    const unsigned base = *pbase;

    if (warp < 8) {
        // ================= CONSUMER (dual recurrence) =================
        const int ks = warp;          // k-slice this warp computes
        const int k0 = ks * 64;
        // Producers of my h slice, per group.
        const unsigned* const fA0 = &g_prog[(gA * 16 + 2 * ks)     * 64];
        const unsigned* const fA1 = &g_prog[(gA * 16 + 2 * ks + 1) * 64];
        const unsigned* const fB0 = &g_prog[(gB * 16 + 2 * ks)     * 64];
        const unsigned* const fB1 = &g_prog[(gB * 16 + 2 * ks + 1) * 64];

        // W_hh[j0+lane][k0..k0+63] -> 32 packed-pair regs (both groups).
        ull w2[32];
        {
            const ulonglong2* wp =
                (const ulonglong2*)(Whh + (size_t)(j0 + lane) * NH + k0);
#pragma unroll
            for (int c = 0; c < 16; ++c) {
                ulonglong2 v = __ldg(wp + c);
                w2[2 * c]     = v.x;
                w2[2 * c + 1] = v.y;
            }
        }

        unsigned pf0 = 0, pf1 = 0;    // full-ring parities (warps 0..3)

        for (int t = 0; t < T_SEQ; ++t) {
            const int slot = t & 1;
            const unsigned need = base + (unsigned)t;
            const float* hprev = t ? hseq + (size_t)(t - 1) * NB * NH : h0;

#pragma unroll
            for (int g = 0; g < 2; ++g) {
                const int gr = g * 4;     // group row offset in hs/ring

                // Dependency wait: this group's 2 producer CTAs at t-1.
                if (t > 0) {
                    flag_wait(g ? fB0 : fA0, need);
                    flag_wait(g ? fB1 : fA1, need);
                }

                // Stage this group's h slice (4 rows x 64 cols).
#pragma unroll
                for (int i = 0; i < 2; ++i) {
                    int idx = lane + 32 * i;       // 0..63 float4 slots
                    int row = idx >> 4;            // 0..3
                    int c4  = idx & 15;
                    float4 v = __ldcg((const float4*)(hprev +
                                  (size_t)(b0 + gr + row) * NH + k0 + c4 * 4));
                    *(float4*)(sm + HS_OFF + (gr + row) * NH + k0 + c4 * 4) = v;
                }
                __syncwarp();

                // 4 partial dots, K-slice 64, packed FMAs, broadcast LDS.
                float accs[4];
#pragma unroll
                for (int b = 0; b < 4; ++b) {
                    const ulonglong2* hp =
                        (const ulonglong2*)(sm + HS_OFF + (gr + b) * NH + k0);
                    ull a0 = 0ull, a1 = 0ull;
#pragma unroll
                    for (int c = 0; c < 16; ++c) {
                        ulonglong2 hv = hp[c];
                        FFMA2(a0, w2[2 * c],     hv.x, a0);
                        FFMA2(a1, w2[2 * c + 1], hv.y, a1);
                    }
                    float2 f0 = unpack2(a0);
                    float2 f1 = unpack2(a1);
                    accs[b] = (f0.x + f0.y) + (f1.x + f1.y);
                }
#pragma unroll
                for (int b = 0; b < 4; ++b)
                    sm[PART_OFF + ks * 128 + b * 32 + lane] = accs[b];
                asm volatile("bar.sync 1, 256;" ::: "memory");

                // Reduce: warps 0..3 (warp = batch within group).
                if (warp < 4) {
                    // Ring slot t becomes readable once per step (group A).
                    if (g == 0) {
                        if (slot) { mbar_wait(a_full0 + 8, pf1); pf1 ^= 1; }
                        else      { mbar_wait(a_full0,     pf0); pf0 ^= 1; }
                    }
                    float s = 0.f;
#pragma unroll
                    for (int w = 0; w < 8; ++w)
                        s += sm[PART_OFF + w * 128 + warp * 32 + lane];
                    const float pre =
                        sm[RING_OFF + slot * 256 + (gr + warp) * 32 + lane];
                    const float hv = tanhf(s + pre);
                    const int   bo = b0 + gr + warp;
                    hseq[((size_t)t * NB + bo) * NH + j0 + lane] = hv;
                    if (t == T_SEQ - 1 && hlast)
                        hlast[(size_t)bo * NH + j0 + lane] = hv;
                }
                asm volatile("bar.sync 1, 256;" ::: "memory");
                if (tid == 0)
                    asm volatile("st.release.gpu.u32 [%0], %1;"
                                 :: "l"(g ? flagB_own : flagA_own),
                                    "r"(base + (unsigned)(t + 1))
                                 : "memory");
            }

            // Both groups read ring slot t -> producers may refill it.
            if (lane == 0) mbar_arrive(a_empty0 + (unsigned)slot * 8);
        }
    } else {
        // ============ PRODUCER (input projection, smem-lean) ============
        const int pw   = warp - 8;    // 0..3
        const int k0   = pw * 64;     // producer k-slice of NI
        const int ptid = tid - 256;   // 0..127

        // W_ih[j0+lane][k0..k0+63] -> 32 packed-pair registers.
        ull wi2[32];
        {
            const ulonglong2* wp =
                (const ulonglong2*)(Wih + (size_t)(j0 + lane) * NI + k0);
#pragma unroll
            for (int c = 0; c < 16; ++c) {
                ulonglong2 v = __ldg(wp + c);
                wi2[2 * c]     = v.x;
                wi2[2 * c + 1] = v.y;
            }
        }
        const float bias = __ldg(bih + j0 + lane) + __ldg(bhh + j0 + lane);
        unsigned pe0 = 0, pe1 = 0;

        for (int t = 0; t < T_SEQ; ++t) {
            const int slot = t & 1;

            // Stage x tile (8 batches x 256) — 128 threads x 4 float4.
#pragma unroll
            for (int i = 0; i < 4; ++i) {
                int idx = ptid + 128 * i;      // 0..511 float4 slots
                int row = idx >> 6;
                int c4  = idx & 63;
                float4 v = __ldg((const float4*)(x +
                              ((size_t)t * NB + b0 + row) * NI + c4 * 4));
                *(float4*)(sm + XB_OFF + row * NI + c4 * 4) = v;
            }
            asm volatile("bar.sync 2, 128;" ::: "memory");

            // 8 partial dots over this warp's 64-k slice (broadcast LDS).
            float pacc[8];
#pragma unroll
            for (int b = 0; b < 8; ++b) {
                const ulonglong2* xp =
                    (const ulonglong2*)(sm + XB_OFF + b * NI + k0);
                ull a0 = 0ull, a1 = 0ull;
#pragma unroll
                for (int c = 0; c < 16; ++c) {
                    ulonglong2 xv = xp[c];
                    FFMA2(a0, wi2[2 * c],     xv.x, a0);
                    FFMA2(a1, wi2[2 * c + 1], xv.y, a1);
                }
                float2 f0 = unpack2(a0);
                float2 f1 = unpack2(a1);
                pacc[b] = (f0.x + f0.y) + (f1.x + f1.y);
            }
#pragma unroll
            for (int b = 0; b < 8; ++b)
                sm[PP_OFF + pw * 256 + b * 32 + lane] = pacc[b];
            asm volatile("bar.sync 2, 128;" ::: "memory");

            // Wait for ring slot to be free (consumers of step t-2 done).
            if (t >= 2) {
                if (slot) { mbar_wait(a_empty0 + 8, pe1); pe1 ^= 1; }
                else      { mbar_wait(a_empty0,     pe0); pe0 ^= 1; }
            }

            // Reduce: warp pw emits batches 2pw and 2pw+1.
#pragma unroll
            for (int r = 0; r < 2; ++r) {
                const int b = pw * 2 + r;
                float s = bias;
#pragma unroll
                for (int w = 0; w < 4; ++w)
                    s += sm[PP_OFF + w * 256 + b * 32 + lane];
                sm[RING_OFF + slot * 256 + b * 32 + lane] = s;
            }
            __syncwarp();
            if (lane == 0) mbar_arrive(a_full0 + (unsigned)slot * 8);
        }
    }
}

// ---------------------------------------------------------------------------
extern "C" void kernel_launch(void* const* d_in, const int* in_sizes, int n_in,
                              void* d_out, int out_size)
{
    const float* x   = (const float*)d_in[0];
    const float* h0  = (const float*)d_in[1];
    const float* Wih = (const float*)d_in[2];
    const float* Whh = (const float*)d_in[3];
    const float* bih = (const float*)d_in[4];
    const float* bhh = (const float*)d_in[5];
    float* out = (float*)d_out;

    float* hlast = nullptr;
    if (out_size >= (int)((size_t)T_SEQ * NB * NH + NB * NH))
        hlast = out + (size_t)T_SEQ * NB * NH;

    const size_t smem = SM_FLOATS * sizeof(float);   // 38976 B
    cudaFuncSetAttribute(rnn_fused,
                         cudaFuncAttributeMaxDynamicSharedMemorySize,
                         (int)smem);
    rnn_fused<<<128, RT, smem>>>(x, h0, Wih, Whh, bih, bhh, out, hlast);
}

// round 14
// speedup vs baseline: 1.2787x; 1.2787x over previous
#include <cuda_runtime.h>
#include <math.h>

#define T_SEQ 512
#define NB    64
#define NI    256
#define NH    512

// Scratch: input projection (64 MB). Progress flags per (group 0..15, jt),
// 256 B apart. MONOTONIC across graph replays: each flag gets exactly +T_SEQ
// per launch from its single writer, so all flags are equal at every launch
// boundary; a CTA reads one of its OWN (not yet written) flags as the base.
__device__ float    g_pre[(size_t)T_SEQ * NB * NH];
__device__ unsigned g_prog[256 * 64];

typedef unsigned long long ull;

// Packed 2x fp32 FMA (sm_10x f32x2 pipe).
#define FFMA2(d, a, b, c) \
    asm("fma.rn.f32x2 %0, %1, %2, %3;" : "=l"(d) : "l"(a), "l"(b), "l"(c))

__device__ __forceinline__ ull pack2(float lo, float hi) {
    ull r;
    asm("mov.b64 %0, {%1, %2};"
        : "=l"(r) : "r"(__float_as_uint(lo)), "r"(__float_as_uint(hi)));
    return r;
}
__device__ __forceinline__ float2 unpack2(ull v) {
    unsigned lo, hi;
    asm("mov.b64 {%0, %1}, %2;" : "=r"(lo), "=r"(hi) : "l"(v));
    return make_float2(__uint_as_float(lo), __uint_as_float(hi));
}
// Poll a progress flag until it reaches `need` (acquire orders later loads).
__device__ __forceinline__ void flag_wait(const unsigned* f, unsigned need) {
    unsigned v;
    do {
        asm volatile("ld.acquire.gpu.u32 %0, [%1];"
                     : "=r"(v) : "l"(f) : "memory");
    } while ((int)(v - need) < 0);
}

// ---------------------------------------------------------------------------
// GEMM: g_pre[m][j] = sum_k x[m][k] * W_ih[j][k] + b_ih[j] + b_hh[j]
// M = T*B = 32768, N = 512, K = 256. Near the fp32 roofline (~250 us).
// ---------------------------------------------------------------------------
#define BM 128
#define BN 64
#define BK 16

__global__ __launch_bounds__(256) void gemm_xw(
    const float* __restrict__ A,    // [M][256]
    const float* __restrict__ Wih,  // [512][256]
    const float* __restrict__ bih,
    const float* __restrict__ bhh)
{
    __shared__ float As[BK][BM + 4];
    __shared__ float Bs[BK][BN + 4];
    const int m0 = blockIdx.y * BM;
    const int n0 = blockIdx.x * BN;
    const int tid = threadIdx.x;
    const int ty = tid >> 4;
    const int tx = tid & 15;

    ull acc2[8][2];
#pragma unroll
    for (int i = 0; i < 8; ++i) { acc2[i][0] = 0ull; acc2[i][1] = 0ull; }

    for (int k0 = 0; k0 < NI; k0 += BK) {
#pragma unroll
        for (int i = 0; i < 2; ++i) {
            int f  = tid + i * 256;
            int r  = f >> 2;
            int c4 = f & 3;
            float4 v = *(const float4*)(A + (size_t)(m0 + r) * NI + k0 + c4 * 4);
            As[c4 * 4 + 0][r] = v.x;
            As[c4 * 4 + 1][r] = v.y;
            As[c4 * 4 + 2][r] = v.z;
            As[c4 * 4 + 3][r] = v.w;
        }
        {
            int r  = tid >> 2;
            int c4 = tid & 3;
            float4 v = *(const float4*)(Wih + (size_t)(n0 + r) * NI + k0 + c4 * 4);
            Bs[c4 * 4 + 0][r] = v.x;
            Bs[c4 * 4 + 1][r] = v.y;
            Bs[c4 * 4 + 2][r] = v.z;
            Bs[c4 * 4 + 3][r] = v.w;
        }
        __syncthreads();
#pragma unroll
        for (int k = 0; k < BK; ++k) {
            float a[8];
            *(float4*)&a[0] = *(const float4*)&As[k][ty * 8];
            *(float4*)&a[4] = *(const float4*)&As[k][ty * 8 + 4];
            ulonglong2 b2 = *(const ulonglong2*)&Bs[k][tx * 4];
#pragma unroll
            for (int i = 0; i < 8; ++i) {
                ull aa = pack2(a[i], a[i]);
                FFMA2(acc2[i][0], aa, b2.x, acc2[i][0]);
                FFMA2(acc2[i][1], aa, b2.y, acc2[i][1]);
            }
        }
        __syncthreads();
    }

    const int n = n0 + tx * 4;
    float4 bias = make_float4(bih[n + 0] + bhh[n + 0], bih[n + 1] + bhh[n + 1],
                              bih[n + 2] + bhh[n + 2], bih[n + 3] + bhh[n + 3]);
#pragma unroll
    for (int i = 0; i < 8; ++i) {
        float2 p0 = unpack2(acc2[i][0]);
        float2 p1 = unpack2(acc2[i][1]);
        float4 o;
        o.x = p0.x + bias.x;
        o.y = p0.y + bias.y;
        o.z = p1.x + bias.z;
        o.w = p1.y + bias.w;
        *(float4*)(g_pre + (size_t)(m0 + ty * 8 + i) * NH + n) = o;
    }
}

// ---------------------------------------------------------------------------
// Recurrence: 128 CTAs x 512 threads = TWO independent 8-warp groups per CTA
// (group g handles 4 batches b0+4g..b0+4g+3, same 32 columns). Groups run
// decoupled step loops with their own named barrier, flags, smem tiles —
// the SMSP scheduler hides one group's cross-CTA handoff latency under the
// other group's dot-product compute (2 A-warps + 2 B-warps per SMSP).
// ---------------------------------------------------------------------------
#define RT 512

__global__ __launch_bounds__(RT, 1) void rnn_recur(
    const float* __restrict__ h0,    // [B][H]
    const float* __restrict__ Whh,   // [H][H]
    float* __restrict__ hseq,        // [T][B][H]
    float* __restrict__ hlast)       // [B][H] or nullptr
{
    __shared__ float hs[2][4 * NH];        // per-group h tile   (16 KB)
    __shared__ float part[2][8 * 4 * 32];  // per-group partials ( 8 KB)
    __shared__ unsigned sbase;

    const int tid  = threadIdx.x;
    const int lane = tid & 31;
    const int warp = tid >> 5;
    const int g    = warp >> 3;           // group 0 / 1
    const int gw   = warp & 7;            // warp within group = k-slice
    const int jt   = blockIdx.x & 15;
    const int bp   = blockIdx.x >> 4;     // batch pair 0..7
    const int j0   = jt * 32;
    const int b0   = bp * 8 + g * 4;      // this group's 4 batch rows
    const int gid  = bp * 2 + g;          // global group id 0..15
    const int k0   = gw * 64;

    unsigned* const flag_own = &g_prog[(gid * 16 + jt) * 64];
    const unsigned* const fA = &g_prog[(gid * 16 + 2 * gw)     * 64];
    const unsigned* const fB = &g_prog[(gid * 16 + 2 * gw + 1) * 64];

    if (tid == 0) sbase = *(volatile unsigned*)flag_own;
    __syncthreads();
    const unsigned base = sbase;

    // W_hh[j0+lane][k0..k0+63] -> 32 packed-pair registers.
    ull w2[32];
    {
        const ulonglong2* wp =
            (const ulonglong2*)(Whh + (size_t)(j0 + lane) * NH + k0);
#pragma unroll
        for (int c = 0; c < 16; ++c) {
            ulonglong2 v = __ldg(wp + c);
            w2[2 * c]     = v.x;
            w2[2 * c + 1] = v.y;
        }
    }

    float* const hsg   = &hs[g][0];
    float* const partg = &part[g][0];
    const int   barid  = 1 + g;           // named barrier per group

    // Reduce-role identity (warps 0..3 of the group): batch row gw, col lane.
    float pre = 0.f;
    if (gw < 4)
        pre = __ldg(g_pre + ((size_t)0 * NB + (b0 + gw)) * NH + j0 + lane);

    for (int t = 0; t < T_SEQ; ++t) {
        // Dependency wait: my slice's 2 producer CTAs at step t-1.
        if (t > 0) {
            const unsigned need = base + (unsigned)t;
            flag_wait(fA, need);
            flag_wait(fB, need);
        }
        const float* hprev = t ? hseq + (size_t)(t - 1) * NB * NH : h0;

        // Stage rows 0-1, then dot them while rows 2-3's LDG is in flight.
        {
            int row = lane >> 4, c4 = lane & 15;
            float4 v0 = __ldcg((const float4*)(hprev +
                           (size_t)(b0 + row) * NH + k0 + c4 * 4));
            float4 v1 = __ldcg((const float4*)(hprev +
                           (size_t)(b0 + 2 + row) * NH + k0 + c4 * 4));
            *(float4*)(hsg + row * NH + k0 + c4 * 4) = v0;
            __syncwarp();

            float accs[4];
#pragma unroll
            for (int b = 0; b < 2; ++b) {
                const ulonglong2* hp =
                    (const ulonglong2*)(hsg + b * NH + k0);
                ull a0 = 0ull, a1 = 0ull;
#pragma unroll
                for (int c = 0; c < 16; ++c) {
                    ulonglong2 hv = hp[c];   // broadcast LDS.128
                    FFMA2(a0, w2[2 * c],     hv.x, a0);
                    FFMA2(a1, w2[2 * c + 1], hv.y, a1);
                }
                float2 f0 = unpack2(a0);
                float2 f1 = unpack2(a1);
                accs[b] = (f0.x + f0.y) + (f1.x + f1.y);
            }

            *(float4*)(hsg + (2 + row) * NH + k0 + c4 * 4) = v1;
            __syncwarp();

#pragma unroll
            for (int b = 2; b < 4; ++b) {
                const ulonglong2* hp =
                    (const ulonglong2*)(hsg + b * NH + k0);
                ull a0 = 0ull, a1 = 0ull;
#pragma unroll
                for (int c = 0; c < 16; ++c) {
                    ulonglong2 hv = hp[c];
                    FFMA2(a0, w2[2 * c],     hv.x, a0);
                    FFMA2(a1, w2[2 * c + 1], hv.y, a1);
                }
                float2 f0 = unpack2(a0);
                float2 f1 = unpack2(a1);
                accs[b] = (f0.x + f0.y) + (f1.x + f1.y);
            }

#pragma unroll
            for (int b = 0; b < 4; ++b)
                partg[gw * 128 + b * 32 + lane] = accs[b];
        }
        asm volatile("bar.sync %0, 256;" :: "r"(barid) : "memory");

        // Reduce + tanh + emit (warps 0..3 of the group).
        if (gw < 4) {
            float s = 0.f;
#pragma unroll
            for (int w = 0; w < 8; ++w)
                s += partg[w * 128 + gw * 32 + lane];
            const float hv = tanhf(s + pre);
            const int   bo = b0 + gw;
            hseq[((size_t)t * NB + bo) * NH + j0 + lane] = hv;
            if (t == T_SEQ - 1 && hlast)
                hlast[(size_t)bo * NH + j0 + lane] = hv;
            // Prefetch next step's pre (off the critical chain).
            if (t + 1 < T_SEQ)
                pre = __ldg(g_pre + ((size_t)(t + 1) * NB + bo) * NH
                            + j0 + lane);
        }
        asm volatile("bar.sync %0, 256;" :: "r"(barid) : "memory");

        // Publish this group's progress (single writer per flag).
        if ((tid & 255) == 0)
            asm volatile("st.release.gpu.u32 [%0], %1;"
                         :: "l"(flag_own), "r"(base + (unsigned)(t + 1))
                         : "memory");
    }
}

// ---------------------------------------------------------------------------
extern "C" void kernel_launch(void* const* d_in, const int* in_sizes, int n_in,
                              void* d_out, int out_size)
{
    const float* x   = (const float*)d_in[0];
    const float* h0  = (const float*)d_in[1];
    const float* Wih = (const float*)d_in[2];
    const float* Whh = (const float*)d_in[3];
    const float* bih = (const float*)d_in[4];
    const float* bhh = (const float*)d_in[5];
    float* out = (float*)d_out;

    float* hlast = nullptr;
    if (out_size >= (int)((size_t)T_SEQ * NB * NH + NB * NH))
        hlast = out + (size_t)T_SEQ * NB * NH;

    dim3 grid(NH / BN, (T_SEQ * NB) / BM);   // (8, 256)
    gemm_xw<<<grid, 256>>>(x, Wih, bih, bhh);

    rnn_recur<<<128, RT>>>(h0, Whh, out, hlast);
}